// round 2
// baseline (speedup 1.0000x reference)
#include <cuda_runtime.h>
#include <math.h>

#define NHID 1024
#define NB 2
#define NS 2048
#define NHEAD 16
#define DH 64
#define NBH (NB * NHEAD)   // 32
#define NM (NB * NS)       // 4096
#define QK_SCALE 0.125f    // 1/sqrt(64)
#define LN_EPS 1e-5f

// ---------------- scratch (static device globals; no allocation allowed) ---
__device__ float g_q[(size_t)NBH * NS * DH];      // [b*h][s][d]  16 MB
__device__ float g_k[(size_t)NBH * NS * DH];
__device__ float g_v[(size_t)NBH * NS * DH];
__device__ float g_ctx[(size_t)NM * NHID];        // [b*s][1024]  16 MB
__device__ float g_tmp[(size_t)NM * NHID];        // pre-LN       16 MB
__device__ float g_rowm[(size_t)NBH * NS];        // softmax row max
__device__ float g_rowl[(size_t)NBH * NS];        // softmax row sum
__device__ float g_scores[(size_t)NBH * NS * NS]; // 512 MB fallback score buf

// ===========================================================================
// K1: QKV projection.  C[m][n] = sum_k X[m][k] * W[n][k]   (x @ W^T)
// Fused N = 3072 (WQ | WK | WV).  128x128 tile, BK=16, 256 thr, 8x8/thread.
// Output written head-major: q/k/v[(b*16+h)*2048 + s][d].
// ===========================================================================
__global__ __launch_bounds__(256) void qkv_kernel(
    const float* __restrict__ X,
    const float* __restrict__ WQ, const float* __restrict__ WK,
    const float* __restrict__ WV)
{
    __shared__ float As[16][132];
    __shared__ float Bs[16][132];

    const int tx = threadIdx.x & 15;
    const int ty = threadIdx.x >> 4;
    const int m0 = blockIdx.y * 128;
    const int nfull = blockIdx.x * 128;     // 0..2944
    const int which = nfull >> 10;          // 0:Q 1:K 2:V
    const float* W = (which == 0) ? WQ : (which == 1) ? WK : WV;
    float* OUT = (which == 0) ? g_q : (which == 1) ? g_k : g_v;
    const int nb0 = nfull & (NHID - 1);

    float acc[8][8];
#pragma unroll
    for (int i = 0; i < 8; i++)
#pragma unroll
        for (int j = 0; j < 8; j++) acc[i][j] = 0.f;

    for (int k0 = 0; k0 < NHID; k0 += 16) {
        __syncthreads();
#pragma unroll
        for (int it = 0; it < 2; it++) {
            int idx = threadIdx.x + it * 256;   // 0..511
            int row = idx >> 2;                 // 0..127
            int c4 = idx & 3;                   // 0..3
            float4 a = *(const float4*)(X + (size_t)(m0 + row) * NHID + k0 + c4 * 4);
            As[c4 * 4 + 0][row] = a.x; As[c4 * 4 + 1][row] = a.y;
            As[c4 * 4 + 2][row] = a.z; As[c4 * 4 + 3][row] = a.w;
            float4 b = *(const float4*)(W + (size_t)(nb0 + row) * NHID + k0 + c4 * 4);
            Bs[c4 * 4 + 0][row] = b.x; Bs[c4 * 4 + 1][row] = b.y;
            Bs[c4 * 4 + 2][row] = b.z; Bs[c4 * 4 + 3][row] = b.w;
        }
        __syncthreads();
#pragma unroll
        for (int kk = 0; kk < 16; kk++) {
            float a[8], b[8];
            *(float4*)&a[0] = *(const float4*)&As[kk][ty * 8];
            *(float4*)&a[4] = *(const float4*)&As[kk][ty * 8 + 4];
            *(float4*)&b[0] = *(const float4*)&Bs[kk][tx * 8];
            *(float4*)&b[4] = *(const float4*)&Bs[kk][tx * 8 + 4];
#pragma unroll
            for (int i = 0; i < 8; i++)
#pragma unroll
                for (int j = 0; j < 8; j++) acc[i][j] += a[i] * b[j];
        }
    }

#pragma unroll
    for (int i = 0; i < 8; i++) {
        int m = m0 + ty * 8 + i;
        int bb = m >> 11;            // /2048
        int s = m & (NS - 1);
#pragma unroll
        for (int jj = 0; jj < 8; jj += 4) {
            int n = nb0 + tx * 8 + jj;
            int h = n >> 6, d = n & 63;
            float4 v = make_float4(acc[i][jj], acc[i][jj + 1], acc[i][jj + 2], acc[i][jj + 3]);
            *(float4*)(OUT + ((size_t)(bb * NHEAD + h) * NS + s) * DH + d) = v;
        }
    }
}

// ===========================================================================
// K2a: scores pass.  Per (bh, 64-q-tile): S = Q K^T * scale, mask -> -1e9,
// write raw scores to sbuf, online rowmax/rowsum (flash-style rescale).
// 256 thr, thread (tx,ty) owns 4x4 of the 64x64 score tile.
// ===========================================================================
__global__ __launch_bounds__(256) void scores_kernel(
    const int* __restrict__ mask, float* __restrict__ sbuf)
{
    const int tx = threadIdx.x & 15;
    const int ty = threadIdx.x >> 4;
    const int q0 = blockIdx.x * 64;
    const int bh = blockIdx.y;
    const int bb = bh >> 4;

    __shared__ float Qs[64][64];   // [d][q]
    __shared__ float Ks[64][64];   // [d][k]

    const float* Qbase = g_q + ((size_t)bh * NS + q0) * DH;
#pragma unroll
    for (int it = 0; it < 4; it++) {
        int idx = threadIdx.x + it * 256;
        int row = idx & 63, c4 = idx >> 6;
        float4 v = *(const float4*)(Qbase + (size_t)row * DH + c4 * 4);
        Qs[c4 * 4 + 0][row] = v.x; Qs[c4 * 4 + 1][row] = v.y;
        Qs[c4 * 4 + 2][row] = v.z; Qs[c4 * 4 + 3][row] = v.w;
    }

    float m_run[4], l_run[4];
#pragma unroll
    for (int i = 0; i < 4; i++) { m_run[i] = -INFINITY; l_run[i] = 0.f; }

    for (int kt = 0; kt < NS / 64; kt++) {
        int k0 = kt * 64;
        __syncthreads();
        const float* Kbase = g_k + ((size_t)bh * NS + k0) * DH;
#pragma unroll
        for (int it = 0; it < 4; it++) {
            int idx = threadIdx.x + it * 256;
            int row = idx & 63, c4 = idx >> 6;
            float4 v = *(const float4*)(Kbase + (size_t)row * DH + c4 * 4);
            Ks[c4 * 4 + 0][row] = v.x; Ks[c4 * 4 + 1][row] = v.y;
            Ks[c4 * 4 + 2][row] = v.z; Ks[c4 * 4 + 3][row] = v.w;
        }
        __syncthreads();

        float acc[4][4];
#pragma unroll
        for (int i = 0; i < 4; i++)
#pragma unroll
            for (int j = 0; j < 4; j++) acc[i][j] = 0.f;

#pragma unroll
        for (int dd = 0; dd < 64; dd++) {
            float4 qv = *(const float4*)&Qs[dd][ty * 4];
            float4 kv = *(const float4*)&Ks[dd][tx * 4];
            acc[0][0] += qv.x * kv.x; acc[0][1] += qv.x * kv.y;
            acc[0][2] += qv.x * kv.z; acc[0][3] += qv.x * kv.w;
            acc[1][0] += qv.y * kv.x; acc[1][1] += qv.y * kv.y;
            acc[1][2] += qv.y * kv.z; acc[1][3] += qv.y * kv.w;
            acc[2][0] += qv.z * kv.x; acc[2][1] += qv.z * kv.y;
            acc[2][2] += qv.z * kv.z; acc[2][3] += qv.z * kv.w;
            acc[3][0] += qv.w * kv.x; acc[3][1] += qv.w * kv.y;
            acc[3][2] += qv.w * kv.z; acc[3][3] += qv.w * kv.w;
        }

#pragma unroll
        for (int i = 0; i < 4; i++) {
            int q = q0 + ty * 4 + i;
            const int4 mk = *(const int4*)(mask + ((size_t)bb * NS + q) * NS + k0 + tx * 4);
            float s0 = acc[i][0] * QK_SCALE; if (mk.x == 0) s0 = -1e9f;
            float s1 = acc[i][1] * QK_SCALE; if (mk.y == 0) s1 = -1e9f;
            float s2 = acc[i][2] * QK_SCALE; if (mk.z == 0) s2 = -1e9f;
            float s3 = acc[i][3] * QK_SCALE; if (mk.w == 0) s3 = -1e9f;
            *(float4*)(sbuf + ((size_t)bh * NS + q) * NS + k0 + tx * 4) =
                make_float4(s0, s1, s2, s3);

            float tm = fmaxf(fmaxf(s0, s1), fmaxf(s2, s3));
#pragma unroll
            for (int o = 8; o > 0; o >>= 1)
                tm = fmaxf(tm, __shfl_xor_sync(0xffffffffu, tm, o, 16));
            float nm = fmaxf(m_run[i], tm);
            float ps = expf(s0 - nm) + expf(s1 - nm) + expf(s2 - nm) + expf(s3 - nm);
#pragma unroll
            for (int o = 8; o > 0; o >>= 1)
                ps += __shfl_xor_sync(0xffffffffu, ps, o, 16);
            l_run[i] = l_run[i] * expf(m_run[i] - nm) + ps;
            m_run[i] = nm;
        }
    }

    if (tx == 0) {
#pragma unroll
        for (int i = 0; i < 4; i++) {
            int q = q0 + ty * 4 + i;
            g_rowm[(size_t)bh * NS + q] = m_run[i];
            g_rowl[(size_t)bh * NS + q] = l_run[i];
        }
    }
}

// ===========================================================================
// K2b: read raw scores, p = exp(s-m)/l, write normalized attn (in place OK),
// accumulate ctx = P @ V.  ctx stored [b*s][1024] (h*64+d) for the out-proj.
// ===========================================================================
__global__ __launch_bounds__(256) void av_kernel(
    const float* __restrict__ sbuf, float* __restrict__ attn_out)
{
    const int tx = threadIdx.x & 15;
    const int ty = threadIdx.x >> 4;
    const int q0 = blockIdx.x * 64;
    const int bh = blockIdx.y;
    const int bb = bh >> 4;
    const int h = bh & 15;

    __shared__ float Ps[64][68];   // [k][q], padded
    __shared__ float Vs[64][64];   // [k][d]

    float mrow[4], linv[4];
#pragma unroll
    for (int i = 0; i < 4; i++) {
        int q = q0 + ty * 4 + i;
        mrow[i] = g_rowm[(size_t)bh * NS + q];
        linv[i] = 1.0f / g_rowl[(size_t)bh * NS + q];
    }

    float acc[4][4];
#pragma unroll
    for (int i = 0; i < 4; i++)
#pragma unroll
        for (int j = 0; j < 4; j++) acc[i][j] = 0.f;

    for (int kt = 0; kt < NS / 64; kt++) {
        int k0 = kt * 64;
        __syncthreads();
        const float* Vbase = g_v + ((size_t)bh * NS + k0) * DH;
#pragma unroll
        for (int it = 0; it < 4; it++) {
            int idx = threadIdx.x + it * 256;
            int c4 = idx & 15, row = idx >> 4;
            float4 v = *(const float4*)(Vbase + (size_t)row * DH + c4 * 4);
            *(float4*)&Vs[row][c4 * 4] = v;
        }
#pragma unroll
        for (int i = 0; i < 4; i++) {
            int q = q0 + ty * 4 + i;
            size_t off = ((size_t)bh * NS + q) * NS + k0 + tx * 4;
            float4 s4 = *(const float4*)(sbuf + off);
            float p0 = expf(s4.x - mrow[i]) * linv[i];
            float p1 = expf(s4.y - mrow[i]) * linv[i];
            float p2 = expf(s4.z - mrow[i]) * linv[i];
            float p3 = expf(s4.w - mrow[i]) * linv[i];
            if (attn_out) *(float4*)(attn_out + off) = make_float4(p0, p1, p2, p3);
            Ps[tx * 4 + 0][ty * 4 + i] = p0;
            Ps[tx * 4 + 1][ty * 4 + i] = p1;
            Ps[tx * 4 + 2][ty * 4 + i] = p2;
            Ps[tx * 4 + 3][ty * 4 + i] = p3;
        }
        __syncthreads();
#pragma unroll
        for (int kk = 0; kk < 64; kk++) {
            float4 pv = *(const float4*)&Ps[kk][ty * 4];
            float4 vv = *(const float4*)&Vs[kk][tx * 4];
            acc[0][0] += pv.x * vv.x; acc[0][1] += pv.x * vv.y;
            acc[0][2] += pv.x * vv.z; acc[0][3] += pv.x * vv.w;
            acc[1][0] += pv.y * vv.x; acc[1][1] += pv.y * vv.y;
            acc[1][2] += pv.y * vv.z; acc[1][3] += pv.y * vv.w;
            acc[2][0] += pv.z * vv.x; acc[2][1] += pv.z * vv.y;
            acc[2][2] += pv.z * vv.z; acc[2][3] += pv.z * vv.w;
            acc[3][0] += pv.w * vv.x; acc[3][1] += pv.w * vv.y;
            acc[3][2] += pv.w * vv.z; acc[3][3] += pv.w * vv.w;
        }
    }

#pragma unroll
    for (int i = 0; i < 4; i++) {
        int q = q0 + ty * 4 + i;
        *(float4*)(g_ctx + ((size_t)(bb * NS + q)) * NHID + h * DH + tx * 4) =
            make_float4(acc[i][0], acc[i][1], acc[i][2], acc[i][3]);
    }
}

// ===========================================================================
// K3: out projection + residual: g_tmp = g_ctx @ WO^T + X
// ===========================================================================
__global__ __launch_bounds__(256) void oproj_kernel(
    const float* __restrict__ WO, const float* __restrict__ X)
{
    __shared__ float As[16][132];
    __shared__ float Bs[16][132];

    const int tx = threadIdx.x & 15;
    const int ty = threadIdx.x >> 4;
    const int m0 = blockIdx.y * 128;
    const int nb0 = blockIdx.x * 128;

    float acc[8][8];
#pragma unroll
    for (int i = 0; i < 8; i++)
#pragma unroll
        for (int j = 0; j < 8; j++) acc[i][j] = 0.f;

    for (int k0 = 0; k0 < NHID; k0 += 16) {
        __syncthreads();
#pragma unroll
        for (int it = 0; it < 2; it++) {
            int idx = threadIdx.x + it * 256;
            int row = idx >> 2, c4 = idx & 3;
            float4 a = *(const float4*)(g_ctx + (size_t)(m0 + row) * NHID + k0 + c4 * 4);
            As[c4 * 4 + 0][row] = a.x; As[c4 * 4 + 1][row] = a.y;
            As[c4 * 4 + 2][row] = a.z; As[c4 * 4 + 3][row] = a.w;
            float4 b = *(const float4*)(WO + (size_t)(nb0 + row) * NHID + k0 + c4 * 4);
            Bs[c4 * 4 + 0][row] = b.x; Bs[c4 * 4 + 1][row] = b.y;
            Bs[c4 * 4 + 2][row] = b.z; Bs[c4 * 4 + 3][row] = b.w;
        }
        __syncthreads();
#pragma unroll
        for (int kk = 0; kk < 16; kk++) {
            float a[8], b[8];
            *(float4*)&a[0] = *(const float4*)&As[kk][ty * 8];
            *(float4*)&a[4] = *(const float4*)&As[kk][ty * 8 + 4];
            *(float4*)&b[0] = *(const float4*)&Bs[kk][tx * 8];
            *(float4*)&b[4] = *(const float4*)&Bs[kk][tx * 8 + 4];
#pragma unroll
            for (int i = 0; i < 8; i++)
#pragma unroll
                for (int j = 0; j < 8; j++) acc[i][j] += a[i] * b[j];
        }
    }

#pragma unroll
    for (int i = 0; i < 8; i++) {
        int m = m0 + ty * 8 + i;
#pragma unroll
        for (int jj = 0; jj < 8; jj += 4) {
            size_t base = (size_t)m * NHID + nb0 + tx * 8 + jj;
            float4 r = *(const float4*)(X + base);
            *(float4*)(g_tmp + base) = make_float4(
                acc[i][jj] + r.x, acc[i][jj + 1] + r.y,
                acc[i][jj + 2] + r.z, acc[i][jj + 3] + r.w);
        }
    }
}

// ===========================================================================
// K4: LayerNorm over last dim (1024), weight=1 bias=0.
// ===========================================================================
__global__ __launch_bounds__(256) void ln_kernel(float* __restrict__ out)
{
    __shared__ float red[8];
    __shared__ float bc;
    int row = blockIdx.x;
    const float* x = g_tmp + (size_t)row * NHID;
    float4 v = *(const float4*)(x + threadIdx.x * 4);

    float s = v.x + v.y + v.z + v.w;
#pragma unroll
    for (int o = 16; o > 0; o >>= 1) s += __shfl_xor_sync(0xffffffffu, s, o);
    if ((threadIdx.x & 31) == 0) red[threadIdx.x >> 5] = s;
    __syncthreads();
    if (threadIdx.x < 32) {
        float t = (threadIdx.x < 8) ? red[threadIdx.x] : 0.f;
#pragma unroll
        for (int o = 4; o > 0; o >>= 1) t += __shfl_xor_sync(0xffffffffu, t, o);
        if (threadIdx.x == 0) bc = t * (1.0f / NHID);
    }
    __syncthreads();
    float mu = bc;
    __syncthreads();

    float dx = v.x - mu, dy = v.y - mu, dz = v.z - mu, dw = v.w - mu;
    float s2 = dx * dx + dy * dy + dz * dz + dw * dw;
#pragma unroll
    for (int o = 16; o > 0; o >>= 1) s2 += __shfl_xor_sync(0xffffffffu, s2, o);
    if ((threadIdx.x & 31) == 0) red[threadIdx.x >> 5] = s2;
    __syncthreads();
    if (threadIdx.x < 32) {
        float t = (threadIdx.x < 8) ? red[threadIdx.x] : 0.f;
#pragma unroll
        for (int o = 4; o > 0; o >>= 1) t += __shfl_xor_sync(0xffffffffu, t, o);
        if (threadIdx.x == 0) bc = rsqrtf(t * (1.0f / NHID) + LN_EPS);
    }
    __syncthreads();
    float rstd = bc;

    *(float4*)(out + (size_t)row * NHID + threadIdx.x * 4) =
        make_float4(dx * rstd, dy * rstd, dz * rstd, dw * rstd);
}

// ===========================================================================
extern "C" void kernel_launch(void* const* d_in, const int* in_sizes, int n_in,
                              void* d_out, int out_size)
{
    const float* X   = (const float*)d_in[0];
    const int*  mask = (const int*)d_in[1];
    const float* WQ  = (const float*)d_in[2];
    const float* WK  = (const float*)d_in[3];
    const float* WV  = (const float*)d_in[4];
    const float* WO  = (const float*)d_in[5];

    const size_t OUT_E = (size_t)NM * NHID;          // 4,194,304
    const size_t ATT_E = (size_t)NBH * NS * NS;      // 134,217,728

    float* outp = nullptr;
    float* attnp = nullptr;
    if ((size_t)out_size >= OUT_E + ATT_E) {
        outp = (float*)d_out;
        attnp = (float*)d_out + OUT_E;
    } else if ((size_t)out_size == ATT_E) {
        attnp = (float*)d_out;
    } else {
        outp = (float*)d_out;
    }

    float* sbuf = attnp;
    if (!sbuf) cudaGetSymbolAddress((void**)&sbuf, g_scores);

    qkv_kernel<<<dim3(3 * NHID / 128, NM / 128), 256>>>(X, WQ, WK, WV);
    scores_kernel<<<dim3(NS / 64, NBH), 256>>>(mask, sbuf);
    av_kernel<<<dim3(NS / 64, NBH), 256>>>(sbuf, attnp);
    if (outp) {
        oproj_kernel<<<dim3(NHID / 128, NM / 128), 256>>>(WO, X);
        ln_kernel<<<NM, 256>>>(outp);
    }
}